// round 11
// baseline (speedup 1.0000x reference)
#include <cuda_runtime.h>
#include <math.h>

// ---------------------------------------------------------------------------
// MS-SSIM on (32,3,512,512) fp32, 5 levels, in (s,d)=(x+y, x-y) basis.
// Two packed f32x2 convolutions per pixel: conv(s,d), conv(s^2,d^2).
// L0,L1,L2: ssim_big tiles (32x64, 256 thr, two half-passes, 39.7KB smem).
// L3+L4: ssim_tail, one block per plane, 47KB smem.
// Reduction: per-block partial stores -> 64-block mid-reduce -> tiny combine.
// ---------------------------------------------------------------------------

#define NC 96
#define L1_PER 65536            // 256*256
#define L2_PER 16384            // 128*128
#define L3_PER 4096             // 64*64
#define OFF_L1 0
#define OFF_L2 (NC * L1_PER)
#define OFF_L3 (OFF_L2 + NC * L2_PER)
#define SD_TOT (OFF_L3 + NC * L3_PER)

#define NPART0 (16 * 8 * NC)    // 12288 L0 blocks
#define NPART1 (8 * 4 * NC)     // 3072 L1 blocks
#define NPART2 (4 * 2 * NC)     // 768 L2 blocks
#define NPARTT (NC * 2)         // 192 tail partials (L3, L4)

__device__ __align__(16) float2 g_sd[SD_TOT];
__device__ float2 g_part0[NPART0];
__device__ float2 g_part1[NPART1];
__device__ float2 g_part2[NPART2];
__device__ float2 g_partT[NPARTT];
__device__ double2 g_mid[64][5];      // [midblock][level] (ssim, cs)

#define GW0 0.12007838424321349f
#define GW1 0.23388075658535032f
#define GW2 0.29208171834287243f
#define C1V (0.01f * 0.01f)
#define C2V (0.03f * 0.03f)

typedef unsigned long long u64;

__device__ __forceinline__ u64 pk2(float lo, float hi) {
    u64 r; asm("mov.b64 %0, {%1, %2};" : "=l"(r) : "f"(lo), "f"(hi)); return r;
}
__device__ __forceinline__ void upk2(u64 v, float& lo, float& hi) {
    asm("mov.b64 {%0, %1}, %2;" : "=f"(lo), "=f"(hi) : "l"(v));
}
__device__ __forceinline__ u64 fma2_(u64 a, u64 b, u64 c) {
    u64 d; asm("fma.rn.f32x2 %0, %1, %2, %3;" : "=l"(d) : "l"(a), "l"(b), "l"(c)); return d;
}
__device__ __forceinline__ u64 mul2_(u64 a, u64 b) {
    u64 d; asm("mul.rn.f32x2 %0, %1, %2;" : "=l"(d) : "l"(a), "l"(b)); return d;
}
__device__ __forceinline__ u64 add2_(u64 a, u64 b) {
    u64 d; asm("add.rn.f32x2 %0, %1, %2;" : "=l"(d) : "l"(a), "l"(b)); return d;
}
__device__ __forceinline__ float rcpa(float x) {
    float r; asm("rcp.approx.f32 %0, %1;" : "=f"(r) : "f"(x)); return r;
}

// SSIM/CS from vertical-conv results: mu=(mu_s,mu_d), sq=(Es2,Ed2)
__device__ __forceinline__ void ssim_px(u64 mu, u64 sq, float& sa, float& ca)
{
    float ms2, md2; upk2(mul2_(mu, mu), ms2, md2);
    float es, ed;  upk2(sq, es, ed);
    float dm = ms2 - md2;          // 4*mu1mu2
    float sm = ms2 + md2;          // 2*(mu1^2+mu2^2)
    float lnum = fmaf(0.5f, dm, C1V);
    float lden = fmaf(0.5f, sm, C1V);
    float csn  = fmaf(0.5f, (es - ed) - dm, C2V);
    float csd  = fmaf(0.5f, (es + ed) - sm, C2V);
    float r = rcpa(csd * lden);
    ca = fmaf(csn * lden, r, ca);
    sa = fmaf(csn * lnum, r, sa);
}

// horizontal 5-tap packed moments (tail kernel)
__device__ __forceinline__ void hmom(const float2* __restrict__ p,
                                     u64 w0p, u64 w1p, u64 w2p,
                                     u64& a_sd, u64& a_sq)
{
    a_sd = 0ull; a_sq = 0ull;
    #pragma unroll
    for (int k = 0; k < 5; k++) {
        u64 v = *reinterpret_cast<const u64*>(p + k);
        u64 wp = (k == 0 || k == 4) ? w0p : ((k == 1 || k == 3) ? w1p : w2p);
        a_sd = fma2_(wp, v, a_sd);
        a_sq = fma2_(wp, mul2_(v, v), a_sq);
    }
}

// ---------------------------------------------------------------------------
// Big-level kernel (levels 0,1,2): 32-wide x 64-tall tile, 256 threads.
// Dynamic smem: s[68][38] float2 (20672B) + hAB[36][33] ulonglong2 (19008B)
// ---------------------------------------------------------------------------
#define BIG_SM_BYTES (68 * 38 * 8 + 36 * 33 * 16)   // 39680

template<bool EXT>
__global__ void __launch_bounds__(256, 5)
ssim_big(const float* __restrict__ ext1, const float* __restrict__ ext2,
         int inOff, int outOff, int W, int H, float2* __restrict__ part)
{
    extern __shared__ __align__(16) char dsm[];
    float2* s = reinterpret_cast<float2*>(dsm);                         // [68][38]
    ulonglong2* hAB = reinterpret_cast<ulonglong2*>(dsm + 68 * 38 * 8); // [36][33]
    __shared__ float red[2][8];

    const int tx = threadIdx.x, ty = threadIdx.y;
    const int tid = ty * 32 + tx;
    const int ox = blockIdx.x * 32, oy = blockIdx.y * 64;
    const int plane = blockIdx.z;

    const u64 w0p = pk2(GW0, GW0), w1p = pk2(GW1, GW1), w2p = pk2(GW2, GW2);

    const size_t planeOff = (size_t)plane * W * H;
    const float2* src = g_sd + inOff + planeOff;   // used when !EXT

    // ---- stage 1: load 68x36 halo as (s,d) into s (stride 38) ----
    bool interior = (ox >= 2) & (oy >= 2) & (ox + 34 <= W) & (oy + 66 <= H);
    if (interior) {
        #pragma unroll
        for (int it = 0; it < 5; it++) {
            int idx = tid + it * 256;
            if (idx < 1224) {
                int r = idx / 18, pc = idx - 18 * r;
                size_t g = (size_t)(oy + r - 2) * W + (ox + 2 * pc - 2);
                if (EXT) {
                    float2 a = *reinterpret_cast<const float2*>(ext1 + planeOff + g);
                    float2 b = *reinterpret_cast<const float2*>(ext2 + planeOff + g);
                    *reinterpret_cast<float4*>(&s[r * 38 + 2 * pc]) =
                        make_float4(a.x + b.x, a.x - b.x, a.y + b.y, a.y - b.y);
                } else {
                    *reinterpret_cast<float4*>(&s[r * 38 + 2 * pc]) =
                        *reinterpret_cast<const float4*>(src + g);
                }
            }
        }
    } else {
        #pragma unroll
        for (int it = 0; it < 10; it++) {
            int idx = tid + it * 256;
            if (idx < 2448) {
                int r = idx / 36, c = idx - 36 * r;
                int gy = oy + r - 2, gx = ox + c - 2;
                float2 v = make_float2(0.f, 0.f);
                if ((gy >= 0) & (gy < H) & (gx >= 0) & (gx < W)) {
                    size_t g = (size_t)gy * W + gx;
                    if (EXT) {
                        float x = ext1[planeOff + g], y = ext2[planeOff + g];
                        v = make_float2(x + y, x - y);
                    } else {
                        v = src[g];
                    }
                }
                s[r * 38 + c] = v;
            }
        }
    }
    __syncthreads();

    // ---- fused 2x2 avg-pool -> next level (reads s only) ----
    {
        int Wh = W >> 1, Hh = H >> 1;
        #pragma unroll
        for (int it = 0; it < 2; it++) {
            int idx = tid + it * 256;
            int pr = idx >> 4, pc = idx & 15;
            int r0 = 2 + 2 * pr, c0 = 2 + 2 * pc;
            u64 a = *reinterpret_cast<const u64*>(&s[r0 * 38 + c0]);
            u64 b = *reinterpret_cast<const u64*>(&s[r0 * 38 + c0 + 1]);
            u64 c = *reinterpret_cast<const u64*>(&s[(r0 + 1) * 38 + c0]);
            u64 d = *reinterpret_cast<const u64*>(&s[(r0 + 1) * 38 + c0 + 1]);
            u64 q = mul2_(pk2(0.25f, 0.25f), add2_(add2_(a, b), add2_(c, d)));
            size_t o = (size_t)outOff + (size_t)plane * Wh * Hh
                     + (size_t)(oy / 2 + pr) * Wh + (ox / 2 + pc);
            *reinterpret_cast<u64*>(&g_sd[o]) = q;
        }
    }

    float sacc = 0.f, cacc = 0.f;

    // ---- two half-passes over the 36-row hAB band ----
    #pragma unroll
    for (int h = 0; h < 2; h++) {
        // stage 2: horizontal moments for halo rows h*32 .. h*32+35
        for (int t = tid; t < 288; t += 256) {
            int g = t / 36;
            int rl = t - 36 * g;
            int j = g * 4;
            const ulonglong2* row =
                reinterpret_cast<const ulonglong2*>(&s[(h * 32 + rl) * 38 + j]);
            u64 v[8];
            #pragma unroll
            for (int q = 0; q < 4; q++) {
                ulonglong2 p = row[q];
                v[2 * q] = p.x; v[2 * q + 1] = p.y;
            }
            u64 vs[8];
            #pragma unroll
            for (int i = 0; i < 8; i++) vs[i] = mul2_(v[i], v[i]);
            #pragma unroll
            for (int o = 0; o < 4; o++) {
                u64 asd = 0ull, asq = 0ull;
                #pragma unroll
                for (int k = 0; k < 5; k++) {
                    u64 wp = (k == 0 || k == 4) ? w0p : ((k == 1 || k == 3) ? w1p : w2p);
                    asd = fma2_(wp, v[o + k], asd);
                    asq = fma2_(wp, vs[o + k], asq);
                }
                hAB[rl * 33 + j + o] = make_ulonglong2(asd, asq);
            }
        }
        __syncthreads();

        // stage 3: vertical ring, 4 output rows per thread
        const int b = ty * 4;
        ulonglong2 ring[5];
        #pragma unroll
        for (int j = 0; j < 5; j++)
            ring[j] = hAB[(b + j) * 33 + tx];

        #pragma unroll
        for (int i = 0; i < 4; i++) {
            if (i > 0) {
                int sl = (i + 4) % 5;
                ring[sl] = hAB[(b + i + 4) * 33 + tx];
            }
            u64 mu = 0ull, sq = 0ull;
            #pragma unroll
            for (int k = 0; k < 5; k++) {
                int sl = (i + k) % 5;
                u64 wp = (k == 0 || k == 4) ? w0p : ((k == 1 || k == 3) ? w1p : w2p);
                mu = fma2_(wp, ring[sl].x, mu);
                sq = fma2_(wp, ring[sl].y, sq);
            }
            ssim_px(mu, sq, sacc, cacc);
        }
        __syncthreads();   // protect hAB before next half overwrites it
    }

    // ---- reduction -> per-block partial store (NO atomics) ----
    #pragma unroll
    for (int off = 16; off; off >>= 1) {
        sacc += __shfl_down_sync(0xffffffffu, sacc, off);
        cacc += __shfl_down_sync(0xffffffffu, cacc, off);
    }
    if (tx == 0) { red[0][ty] = sacc; red[1][ty] = cacc; }
    __syncthreads();
    if (tid == 0) {
        float ss = 0.f, cc = 0.f;
        #pragma unroll
        for (int i = 0; i < 8; i++) { ss += red[0][i]; cc += red[1][i]; }
        int bid = blockIdx.x + gridDim.x * (blockIdx.y + gridDim.y * blockIdx.z);
        part[bid] = make_float2(ss, cc);
    }
}

// ---------------------------------------------------------------------------
// Plane SSIM helper (tail kernel): per-column hmom + vertical ring.
// NW warps, 32 threads/warp.
// ---------------------------------------------------------------------------
template<int S, int NW>
__device__ __forceinline__ void ssim_plane(const float2* __restrict__ P, int stride,
                                           int tx, int ty, float& sa, float& ca)
{
    constexpr int RPT = S / NW;
    const u64 w0p = pk2(GW0, GW0), w1p = pk2(GW1, GW1), w2p = pk2(GW2, GW2);

    #pragma unroll
    for (int ct = 0; ct < S / 32; ct++) {
        int c = tx + 32 * ct;
        int r0 = ty * RPT;
        u64 m_sd[5], m_sq[5];

        #pragma unroll
        for (int j = 0; j < 5; j++)
            hmom(P + (r0 + j) * stride + c, w0p, w1p, w2p, m_sd[j], m_sq[j]);

        #pragma unroll
        for (int i = 0; i < RPT; i++) {
            if (i > 0) {
                int sl = (i + 4) % 5;
                hmom(P + (r0 + i + 4) * stride + c, w0p, w1p, w2p, m_sd[sl], m_sq[sl]);
            }
            u64 mu = 0ull, sq = 0ull;
            #pragma unroll
            for (int k = 0; k < 5; k++) {
                int sl = (i + k) % 5;
                u64 wp = (k == 0 || k == 4) ? w0p : ((k == 1 || k == 3) ? w1p : w2p);
                mu = fma2_(wp, m_sd[sl], mu);
                sq = fma2_(wp, m_sq[sl], sq);
            }
            ssim_px(mu, sq, sa, ca);
        }
    }
}

// ---------------------------------------------------------------------------
// Tail kernel: levels 3,4 — one block per plane, 256 threads, 47.4KB smem.
//   A: 68x68 float2 (64+halo), B: 36x36 float2 (32+halo)
// ---------------------------------------------------------------------------
#define TAIL_SM_BYTES (68 * 68 * 8 + 36 * 36 * 8)   // 47360

__global__ void __launch_bounds__(256)
ssim_tail()
{
    extern __shared__ __align__(16) float2 sm[];
    float2* A = sm;                 // [68][68]
    float2* B = sm + 68 * 68;       // [36][36]
    __shared__ float red[4][8];

    const int tx = threadIdx.x, ty = threadIdx.y;
    const int tid = ty * 32 + tx;
    const int plane = blockIdx.x;

    const float2* src = g_sd + OFF_L3 + (size_t)plane * L3_PER;

    // zero B fully and A borders
    for (int idx = tid; idx < 1296; idx += 256) B[idx] = make_float2(0.f, 0.f);
    for (int idx = tid; idx < 528; idx += 256) {
        int o;
        if (idx < 272) {
            int rr = idx / 68, c = idx - 68 * rr;
            int rows4[4] = {0, 1, 66, 67};
            o = rows4[rr] * 68 + c;
        } else {
            int k = idx - 272;
            int r = 2 + (k >> 2);
            int cols4[4] = {0, 1, 66, 67};
            o = r * 68 + cols4[k & 3];
        }
        A[o] = make_float2(0.f, 0.f);
    }
    // load A interior: 64 rows x 32 float4
    for (int idx = tid; idx < 2048; idx += 256) {
        int r = idx >> 5, c4 = idx & 31;
        *reinterpret_cast<float4*>(&A[(r + 2) * 68 + 2 + 2 * c4]) =
            *reinterpret_cast<const float4*>(src + r * 64 + 2 * c4);
    }
    __syncthreads();

    float s3 = 0.f, c3 = 0.f, s4 = 0.f, c4v = 0.f;

    ssim_plane<64, 8>(A, 68, tx, ty, s3, c3);
    // pool A -> B interior (32x32)
    for (int idx = tid; idx < 1024; idx += 256) {
        int i = idx >> 5, j = idx & 31;
        int base = (2 * i + 2) * 68 + (2 * j + 2);
        u64 a = *reinterpret_cast<const u64*>(&A[base]);
        u64 b = *reinterpret_cast<const u64*>(&A[base + 1]);
        u64 c = *reinterpret_cast<const u64*>(&A[base + 68]);
        u64 d = *reinterpret_cast<const u64*>(&A[base + 69]);
        *reinterpret_cast<u64*>(&B[(i + 2) * 36 + j + 2]) =
            mul2_(pk2(0.25f, 0.25f), add2_(add2_(a, b), add2_(c, d)));
    }
    __syncthreads();

    ssim_plane<32, 8>(B, 36, tx, ty, s4, c4v);

    float vals[4] = {s3, c3, s4, c4v};
    #pragma unroll
    for (int v = 0; v < 4; v++) {
        float x = vals[v];
        #pragma unroll
        for (int off = 16; off; off >>= 1)
            x += __shfl_down_sync(0xffffffffu, x, off);
        if (tx == 0) red[v][ty] = x;
    }
    __syncthreads();
    if (tid == 0) {
        float t[4] = {0.f, 0.f, 0.f, 0.f};
        #pragma unroll
        for (int i = 0; i < 8; i++)
            #pragma unroll
            for (int v = 0; v < 4; v++) t[v] += red[v][i];
        g_partT[plane * 2 + 0] = make_float2(t[0], t[1]);
        g_partT[plane * 2 + 1] = make_float2(t[2], t[3]);
    }
}

// ---------------------------------------------------------------------------
// Mid-reduce: 64 blocks x 256 threads; own slot -> no atomics.
// ---------------------------------------------------------------------------
__global__ void __launch_bounds__(256)
mid_reduce()
{
    const int tid = threadIdx.x, bid = blockIdx.x;
    const int lane = tid & 31, warp = tid >> 5;
    const int g = bid * 256 + tid;       // 0..16383
    __shared__ double sh[10][8];

    double s[5] = {0, 0, 0, 0, 0}, c[5] = {0, 0, 0, 0, 0};
    if (g < NPART0) { float2 v = g_part0[g]; s[0] = v.x; c[0] = v.y; }
    if (g < NPART1) { float2 v = g_part1[g]; s[1] = v.x; c[1] = v.y; }
    if (g < NPART2) { float2 v = g_part2[g]; s[2] = v.x; c[2] = v.y; }
    if (g < NPARTT) {
        float2 v = g_partT[g];
        int l = 3 + (g & 1);
        s[l] = v.x; c[l] = v.y;
    }

    #pragma unroll
    for (int l = 0; l < 5; l++) {
        double x = s[l], y = c[l];
        #pragma unroll
        for (int off = 16; off; off >>= 1) {
            x += __shfl_down_sync(0xffffffffu, x, off);
            y += __shfl_down_sync(0xffffffffu, y, off);
        }
        if (lane == 0) { sh[l][warp] = x; sh[5 + l][warp] = y; }
    }
    __syncthreads();
    if (tid < 5) {
        double x = 0, y = 0;
        #pragma unroll
        for (int w = 0; w < 8; w++) { x += sh[tid][w]; y += sh[5 + tid][w]; }
        g_mid[bid][tid] = make_double2(x, y);
    }
}

// ---------------------------------------------------------------------------
// Final combine.
// ---------------------------------------------------------------------------
__global__ void __launch_bounds__(64)
final_combine(float* __restrict__ out)
{
    const int tid = threadIdx.x;      // 0..63
    const int lane = tid & 31, warp = tid >> 5;
    __shared__ double sh[10][2];

    double s[5], c[5];
    #pragma unroll
    for (int l = 0; l < 5; l++) {
        double2 v = g_mid[tid][l];
        s[l] = v.x; c[l] = v.y;
    }
    #pragma unroll
    for (int l = 0; l < 5; l++) {
        double x = s[l], y = c[l];
        #pragma unroll
        for (int off = 16; off; off >>= 1) {
            x += __shfl_down_sync(0xffffffffu, x, off);
            y += __shfl_down_sync(0xffffffffu, y, off);
        }
        if (lane == 0) { sh[l][warp] = x; sh[5 + l][warp] = y; }
    }
    __syncthreads();
    if (tid == 0) {
        double S[5], C[5];
        #pragma unroll
        for (int l = 0; l < 5; l++) {
            S[l] = sh[l][0] + sh[l][1];
            C[l] = sh[5 + l][0] + sh[5 + l][1];
        }
        const double w[5] = {(double)0.0448f, (double)0.2856f, (double)0.3001f,
                             (double)0.2363f, (double)0.1333f};
        double cnt4 = (double)NC * 32.0 * 32.0;
        double ss4 = (S[4] / cnt4 + 1.0) * 0.5;
        double p2 = pow(ss4, w[4]);

        double res = 1.0;
        #pragma unroll
        for (int i = 0; i < 4; i++) {
            int dim = 512 >> i;
            double cnt = (double)NC * (double)dim * (double)dim;
            double m = (C[i] / cnt + 1.0) * 0.5;
            res *= pow(m, w[i]) * p2;
        }
        out[0] = (float)res;
    }
}

extern "C" void kernel_launch(void* const* d_in, const int* in_sizes, int n_in,
                              void* d_out, int out_size)
{
    const float* img1 = (const float*)d_in[0];
    const float* img2 = (const float*)d_in[1];
    float* out = (float*)d_out;

    cudaFuncSetAttribute(ssim_big<true>,
                         cudaFuncAttributeMaxDynamicSharedMemorySize, BIG_SM_BYTES);
    cudaFuncSetAttribute(ssim_big<false>,
                         cudaFuncAttributeMaxDynamicSharedMemorySize, BIG_SM_BYTES);
    cudaFuncSetAttribute(ssim_tail,
                         cudaFuncAttributeMaxDynamicSharedMemorySize, TAIL_SM_BYTES);

    float2* part0; cudaGetSymbolAddress((void**)&part0, g_part0);
    float2* part1; cudaGetSymbolAddress((void**)&part1, g_part1);
    float2* part2; cudaGetSymbolAddress((void**)&part2, g_part2);

    dim3 blk(32, 8);
    ssim_big<true><<<dim3(16, 8, NC), blk, BIG_SM_BYTES>>>(img1, img2, 0, OFF_L1, 512, 512, part0);
    ssim_big<false><<<dim3(8, 4, NC), blk, BIG_SM_BYTES>>>(nullptr, nullptr, OFF_L1, OFF_L2, 256, 256, part1);
    ssim_big<false><<<dim3(4, 2, NC), blk, BIG_SM_BYTES>>>(nullptr, nullptr, OFF_L2, OFF_L3, 128, 128, part2);
    ssim_tail<<<NC, blk, TAIL_SM_BYTES>>>();
    mid_reduce<<<64, 256>>>();
    final_combine<<<1, 64>>>(out);
}

// round 12
// speedup vs baseline: 1.1361x; 1.1361x over previous
#include <cuda_runtime.h>
#include <math.h>

// ---------------------------------------------------------------------------
// MS-SSIM on (32,3,512,512) fp32, 5 levels, in (s,d)=(x+y, x-y) basis.
// ssim_big (L0..L3): 32x64 tile, NO input smem tile — stage-2 and pool read
//   global directly (L1-cached); only the 19KB hAB moment band lives in smem.
//   STS bank conflicts avoided by logical column permutation c=4g+o -> p=g+8o
//   (stage-3 sums over all columns, so the permutation is invisible).
// ssim_tail (L4): one block per plane, 10KB smem.
// Reduction: per-block partial stores -> 48-block mid-reduce -> tiny combine.
// ---------------------------------------------------------------------------

#define NC 96
#define L1_PER 65536            // 256*256
#define L2_PER 16384            // 128*128
#define L3_PER 4096             // 64*64
#define L4_PER 1024             // 32*32
#define OFF_L1 0
#define OFF_L2 (NC * L1_PER)
#define OFF_L3 (OFF_L2 + NC * L2_PER)
#define OFF_L4 (OFF_L3 + NC * L3_PER)
#define SD_TOT (OFF_L4 + NC * L4_PER)

#define NPART0 (16 * 8 * NC)    // 12288
#define NPART1 (8 * 4 * NC)     // 3072
#define NPART2 (4 * 2 * NC)     // 768
#define NPART3 (2 * 1 * NC)     // 192
#define NPART4 NC               // 96

__device__ __align__(16) float2 g_sd[SD_TOT];
__device__ float2 g_part0[NPART0];
__device__ float2 g_part1[NPART1];
__device__ float2 g_part2[NPART2];
__device__ float2 g_part3[NPART3];
__device__ float2 g_part4[NPART4];
__device__ double2 g_mid[48][5];

#define GW0 0.12007838424321349f
#define GW1 0.23388075658535032f
#define GW2 0.29208171834287243f
#define C1V (0.01f * 0.01f)
#define C2V (0.03f * 0.03f)

typedef unsigned long long u64;

__device__ __forceinline__ u64 pk2(float lo, float hi) {
    u64 r; asm("mov.b64 %0, {%1, %2};" : "=l"(r) : "f"(lo), "f"(hi)); return r;
}
__device__ __forceinline__ void upk2(u64 v, float& lo, float& hi) {
    asm("mov.b64 {%0, %1}, %2;" : "=f"(lo), "=f"(hi) : "l"(v));
}
__device__ __forceinline__ u64 fma2_(u64 a, u64 b, u64 c) {
    u64 d; asm("fma.rn.f32x2 %0, %1, %2, %3;" : "=l"(d) : "l"(a), "l"(b), "l"(c)); return d;
}
__device__ __forceinline__ u64 mul2_(u64 a, u64 b) {
    u64 d; asm("mul.rn.f32x2 %0, %1, %2;" : "=l"(d) : "l"(a), "l"(b)); return d;
}
__device__ __forceinline__ u64 add2_(u64 a, u64 b) {
    u64 d; asm("add.rn.f32x2 %0, %1, %2;" : "=l"(d) : "l"(a), "l"(b)); return d;
}
__device__ __forceinline__ float rcpa(float x) {
    float r; asm("rcp.approx.f32 %0, %1;" : "=f"(r) : "f"(x)); return r;
}

__device__ __forceinline__ void ssim_px(u64 mu, u64 sq, float& sa, float& ca)
{
    float ms2, md2; upk2(mul2_(mu, mu), ms2, md2);
    float es, ed;  upk2(sq, es, ed);
    float dm = ms2 - md2;
    float sm = ms2 + md2;
    float lnum = fmaf(0.5f, dm, C1V);
    float lden = fmaf(0.5f, sm, C1V);
    float csn  = fmaf(0.5f, (es - ed) - dm, C2V);
    float csd  = fmaf(0.5f, (es + ed) - sm, C2V);
    float r = rcpa(csd * lden);
    ca = fmaf(csn * lden, r, ca);
    sa = fmaf(csn * lnum, r, sa);
}

// horizontal 5-tap packed moments (tail kernel only)
__device__ __forceinline__ void hmom(const float2* __restrict__ p,
                                     u64 w0p, u64 w1p, u64 w2p,
                                     u64& a_sd, u64& a_sq)
{
    a_sd = 0ull; a_sq = 0ull;
    #pragma unroll
    for (int k = 0; k < 5; k++) {
        u64 v = *reinterpret_cast<const u64*>(p + k);
        u64 wp = (k == 0 || k == 4) ? w0p : ((k == 1 || k == 3) ? w1p : w2p);
        a_sd = fma2_(wp, v, a_sd);
        a_sq = fma2_(wp, mul2_(v, v), a_sq);
    }
}

// ---------------------------------------------------------------------------
// Big-level kernel (levels 0..3): 32-wide x 64-tall tile, 256 threads.
// smem: hAB[36][33] ulonglong2 = 19008 B only.
// ---------------------------------------------------------------------------
template<bool EXT>
__global__ void __launch_bounds__(256, 6)
ssim_big(const float* __restrict__ ext1, const float* __restrict__ ext2,
         int inOff, int outOff, int W, int H, float2* __restrict__ part)
{
    __shared__ ulonglong2 hAB[36 * 33];
    __shared__ float red[2][8];

    const int tx = threadIdx.x, ty = threadIdx.y;
    const int tid = ty * 32 + tx;
    const int ox = blockIdx.x * 32, oy = blockIdx.y * 64;
    const int plane = blockIdx.z;

    const u64 w0p = pk2(GW0, GW0), w1p = pk2(GW1, GW1), w2p = pk2(GW2, GW2);
    const u64 quarter = pk2(0.25f, 0.25f);

    const size_t planeOff = (size_t)plane * W * H;
    const float2* src = g_sd + inOff + planeOff;   // used when !EXT
    const float* p1 = EXT ? (ext1 + planeOff) : nullptr;
    const float* p2 = EXT ? (ext2 + planeOff) : nullptr;

    // ---- fused 2x2 avg-pool (direct from global; region always in-image) ----
    {
        int pr = tid >> 3, pc2 = tid & 7;    // input rows oy+2pr..+1, cols ox+4pc2..+3
        int Wh = W >> 1;
        size_t o = (size_t)outOff + (size_t)plane * (Wh * (H >> 1))
                 + (size_t)(oy / 2 + pr) * Wh + (ox / 2) + 2 * pc2;
        if (EXT) {
            const float* q1 = p1 + (size_t)(oy + 2 * pr) * W + ox + 4 * pc2;
            const float* q2 = p2 + (size_t)(oy + 2 * pr) * W + ox + 4 * pc2;
            float4 a0 = *reinterpret_cast<const float4*>(q1);
            float4 a1 = *reinterpret_cast<const float4*>(q1 + W);
            float4 b0 = *reinterpret_cast<const float4*>(q2);
            float4 b1 = *reinterpret_cast<const float4*>(q2 + W);
            float sA0 = a0.x + a0.y + a1.x + a1.y;
            float sA1 = a0.z + a0.w + a1.z + a1.w;
            float sB0 = b0.x + b0.y + b1.x + b1.y;
            float sB1 = b0.z + b0.w + b1.z + b1.w;
            float4 outv = make_float4(0.25f * (sA0 + sB0), 0.25f * (sA0 - sB0),
                                      0.25f * (sA1 + sB1), 0.25f * (sA1 - sB1));
            *reinterpret_cast<float4*>(&g_sd[o]) = outv;
        } else {
            const float2* q = src + (size_t)(oy + 2 * pr) * W + ox + 4 * pc2;
            ulonglong2 A = *reinterpret_cast<const ulonglong2*>(q);
            ulonglong2 B = *reinterpret_cast<const ulonglong2*>(q + 2);
            ulonglong2 C = *reinterpret_cast<const ulonglong2*>(q + W);
            ulonglong2 D = *reinterpret_cast<const ulonglong2*>(q + W + 2);
            ulonglong2 outv;
            outv.x = mul2_(quarter, add2_(add2_(A.x, A.y), add2_(C.x, C.y)));
            outv.y = mul2_(quarter, add2_(add2_(B.x, B.y), add2_(D.x, D.y)));
            *reinterpret_cast<ulonglong2*>(&g_sd[o]) = outv;
        }
    }

    float sacc = 0.f, cacc = 0.f;

    #pragma unroll
    for (int h = 0; h < 2; h++) {
        // ---- stage 2: horizontal moments, direct global loads ----
        // 288 tasks: t = rl*8 + g ; rl in 0..35 (halo rows), g in 0..7 (col group)
        for (int t = tid; t < 288; t += 256) {
            int rl = t >> 3, g = t & 7;
            int gy = oy + h * 32 + rl - 2;
            int c0 = ox + 4 * g - 2;             // first needed input col
            u64 v[8];
            if ((gy >= 0) & (gy < H)) {
                if (EXT) {
                    if (c0 >= 2 && c0 + 9 < W) {
                        const float* q1 = p1 + (size_t)gy * W + (c0 - 2);
                        const float* q2 = p2 + (size_t)gy * W + (c0 - 2);
                        float4 A0 = *reinterpret_cast<const float4*>(q1);
                        float4 B0 = *reinterpret_cast<const float4*>(q2);
                        v[0] = pk2(A0.z + B0.z, A0.z - B0.z);
                        v[1] = pk2(A0.w + B0.w, A0.w - B0.w);
                        float4 A1 = *reinterpret_cast<const float4*>(q1 + 4);
                        float4 B1 = *reinterpret_cast<const float4*>(q2 + 4);
                        v[2] = pk2(A1.x + B1.x, A1.x - B1.x);
                        v[3] = pk2(A1.y + B1.y, A1.y - B1.y);
                        v[4] = pk2(A1.z + B1.z, A1.z - B1.z);
                        v[5] = pk2(A1.w + B1.w, A1.w - B1.w);
                        float4 A2 = *reinterpret_cast<const float4*>(q1 + 8);
                        float4 B2 = *reinterpret_cast<const float4*>(q2 + 8);
                        v[6] = pk2(A2.x + B2.x, A2.x - B2.x);
                        v[7] = pk2(A2.y + B2.y, A2.y - B2.y);
                    } else {
                        #pragma unroll
                        for (int e = 0; e < 8; e++) {
                            int c = c0 + e;
                            float av = 0.f, bv = 0.f;
                            if ((c >= 0) & (c < W)) {
                                size_t ix = (size_t)gy * W + c;
                                av = p1[ix]; bv = p2[ix];
                            }
                            v[e] = pk2(av + bv, av - bv);
                        }
                    }
                } else {
                    if (c0 >= 0 && c0 + 8 <= W) {
                        const ulonglong2* q =
                            reinterpret_cast<const ulonglong2*>(src + (size_t)gy * W + c0);
                        ulonglong2 q0 = q[0], q1v = q[1], q2v = q[2], q3v = q[3];
                        v[0] = q0.x;  v[1] = q0.y;
                        v[2] = q1v.x; v[3] = q1v.y;
                        v[4] = q2v.x; v[5] = q2v.y;
                        v[6] = q3v.x; v[7] = q3v.y;
                    } else {
                        #pragma unroll
                        for (int e = 0; e < 8; e++) {
                            int c = c0 + e;
                            v[e] = ((c >= 0) & (c < W))
                                 ? *reinterpret_cast<const u64*>(src + (size_t)gy * W + c)
                                 : 0ull;
                        }
                    }
                }
            } else {
                #pragma unroll
                for (int e = 0; e < 8; e++) v[e] = 0ull;
            }

            u64 vs[8];
            #pragma unroll
            for (int i = 0; i < 8; i++) vs[i] = mul2_(v[i], v[i]);
            #pragma unroll
            for (int o = 0; o < 4; o++) {
                u64 asd = 0ull, asq = 0ull;
                #pragma unroll
                for (int k = 0; k < 5; k++) {
                    u64 wp = (k == 0 || k == 4) ? w0p : ((k == 1 || k == 3) ? w1p : w2p);
                    asd = fma2_(wp, v[o + k], asd);
                    asq = fma2_(wp, vs[o + k], asq);
                }
                // logical col 4g+o stored at physical col g+8o (bank-conflict-free;
                // stage 3 sums over all columns so the permutation is harmless)
                hAB[rl * 33 + g + 8 * o] = make_ulonglong2(asd, asq);
            }
        }
        __syncthreads();

        // ---- stage 3: vertical ring, 4 output rows per thread ----
        const int b = ty * 4;
        ulonglong2 ring[5];
        #pragma unroll
        for (int j = 0; j < 5; j++)
            ring[j] = hAB[(b + j) * 33 + tx];

        #pragma unroll
        for (int i = 0; i < 4; i++) {
            if (i > 0) {
                int sl = (i + 4) % 5;
                ring[sl] = hAB[(b + i + 4) * 33 + tx];
            }
            u64 mu = 0ull, sq = 0ull;
            #pragma unroll
            for (int k = 0; k < 5; k++) {
                int sl = (i + k) % 5;
                u64 wp = (k == 0 || k == 4) ? w0p : ((k == 1 || k == 3) ? w1p : w2p);
                mu = fma2_(wp, ring[sl].x, mu);
                sq = fma2_(wp, ring[sl].y, sq);
            }
            ssim_px(mu, sq, sacc, cacc);
        }
        __syncthreads();
    }

    // ---- reduction -> per-block partial store ----
    #pragma unroll
    for (int off = 16; off; off >>= 1) {
        sacc += __shfl_down_sync(0xffffffffu, sacc, off);
        cacc += __shfl_down_sync(0xffffffffu, cacc, off);
    }
    if (tx == 0) { red[0][ty] = sacc; red[1][ty] = cacc; }
    __syncthreads();
    if (tid == 0) {
        float ss = 0.f, cc = 0.f;
        #pragma unroll
        for (int i = 0; i < 8; i++) { ss += red[0][i]; cc += red[1][i]; }
        int bid = blockIdx.x + gridDim.x * (blockIdx.y + gridDim.y * blockIdx.z);
        part[bid] = make_float2(ss, cc);
    }
}

// ---------------------------------------------------------------------------
// Plane SSIM helper (tail): per-column hmom + vertical ring.
// ---------------------------------------------------------------------------
template<int S, int NW>
__device__ __forceinline__ void ssim_plane(const float2* __restrict__ P, int stride,
                                           int tx, int ty, float& sa, float& ca)
{
    constexpr int RPT = S / NW;
    const u64 w0p = pk2(GW0, GW0), w1p = pk2(GW1, GW1), w2p = pk2(GW2, GW2);

    #pragma unroll
    for (int ct = 0; ct < S / 32; ct++) {
        int c = tx + 32 * ct;
        int r0 = ty * RPT;
        u64 m_sd[5], m_sq[5];

        #pragma unroll
        for (int j = 0; j < 5; j++)
            hmom(P + (r0 + j) * stride + c, w0p, w1p, w2p, m_sd[j], m_sq[j]);

        #pragma unroll
        for (int i = 0; i < RPT; i++) {
            if (i > 0) {
                int sl = (i + 4) % 5;
                hmom(P + (r0 + i + 4) * stride + c, w0p, w1p, w2p, m_sd[sl], m_sq[sl]);
            }
            u64 mu = 0ull, sq = 0ull;
            #pragma unroll
            for (int k = 0; k < 5; k++) {
                int sl = (i + k) % 5;
                u64 wp = (k == 0 || k == 4) ? w0p : ((k == 1 || k == 3) ? w1p : w2p);
                mu = fma2_(wp, m_sd[sl], mu);
                sq = fma2_(wp, m_sq[sl], sq);
            }
            ssim_px(mu, sq, sa, ca);
        }
    }
}

// ---------------------------------------------------------------------------
// Tail kernel: level 4 only — one block per plane, 256 threads, 10.4KB smem.
// ---------------------------------------------------------------------------
__global__ void __launch_bounds__(256)
ssim_tail()
{
    __shared__ __align__(16) float2 A[36 * 36];
    __shared__ float red[2][8];

    const int tx = threadIdx.x, ty = threadIdx.y;
    const int tid = ty * 32 + tx;
    const int plane = blockIdx.x;

    const float2* src = g_sd + OFF_L4 + (size_t)plane * L4_PER;

    for (int idx = tid; idx < 1296; idx += 256) A[idx] = make_float2(0.f, 0.f);
    __syncthreads();
    for (int idx = tid; idx < 512; idx += 256) {
        int r = idx >> 4, c4 = idx & 15;
        *reinterpret_cast<float4*>(&A[(r + 2) * 36 + 2 + 2 * c4]) =
            *reinterpret_cast<const float4*>(src + r * 32 + 2 * c4);
    }
    __syncthreads();

    float s4 = 0.f, c4v = 0.f;
    ssim_plane<32, 8>(A, 36, tx, ty, s4, c4v);

    #pragma unroll
    for (int off = 16; off; off >>= 1) {
        s4  += __shfl_down_sync(0xffffffffu, s4, off);
        c4v += __shfl_down_sync(0xffffffffu, c4v, off);
    }
    if (tx == 0) { red[0][ty] = s4; red[1][ty] = c4v; }
    __syncthreads();
    if (tid == 0) {
        float ss = 0.f, cc = 0.f;
        #pragma unroll
        for (int i = 0; i < 8; i++) { ss += red[0][i]; cc += red[1][i]; }
        g_part4[plane] = make_float2(ss, cc);
    }
}

// ---------------------------------------------------------------------------
// Mid-reduce: 48 blocks x 256 threads; own slot -> no atomics.
// ---------------------------------------------------------------------------
__global__ void __launch_bounds__(256)
mid_reduce()
{
    const int tid = threadIdx.x, bid = blockIdx.x;
    const int lane = tid & 31, warp = tid >> 5;
    const int g = bid * 256 + tid;       // 0..12287
    __shared__ double sh[10][8];

    double s[5] = {0, 0, 0, 0, 0}, c[5] = {0, 0, 0, 0, 0};
    { float2 v = g_part0[g]; s[0] = v.x; c[0] = v.y; }
    if (g < NPART1) { float2 v = g_part1[g]; s[1] = v.x; c[1] = v.y; }
    if (g < NPART2) { float2 v = g_part2[g]; s[2] = v.x; c[2] = v.y; }
    if (g < NPART3) { float2 v = g_part3[g]; s[3] = v.x; c[3] = v.y; }
    if (g < NPART4) { float2 v = g_part4[g]; s[4] = v.x; c[4] = v.y; }

    #pragma unroll
    for (int l = 0; l < 5; l++) {
        double x = s[l], y = c[l];
        #pragma unroll
        for (int off = 16; off; off >>= 1) {
            x += __shfl_down_sync(0xffffffffu, x, off);
            y += __shfl_down_sync(0xffffffffu, y, off);
        }
        if (lane == 0) { sh[l][warp] = x; sh[5 + l][warp] = y; }
    }
    __syncthreads();
    if (tid < 5) {
        double x = 0, y = 0;
        #pragma unroll
        for (int w = 0; w < 8; w++) { x += sh[tid][w]; y += sh[5 + tid][w]; }
        g_mid[bid][tid] = make_double2(x, y);
    }
}

__global__ void __launch_bounds__(64)
final_combine(float* __restrict__ out)
{
    const int tid = threadIdx.x;
    const int lane = tid & 31, warp = tid >> 5;
    __shared__ double sh[10][2];

    double s[5] = {0, 0, 0, 0, 0}, c[5] = {0, 0, 0, 0, 0};
    if (tid < 48) {
        #pragma unroll
        for (int l = 0; l < 5; l++) {
            double2 v = g_mid[tid][l];
            s[l] = v.x; c[l] = v.y;
        }
    }
    #pragma unroll
    for (int l = 0; l < 5; l++) {
        double x = s[l], y = c[l];
        #pragma unroll
        for (int off = 16; off; off >>= 1) {
            x += __shfl_down_sync(0xffffffffu, x, off);
            y += __shfl_down_sync(0xffffffffu, y, off);
        }
        if (lane == 0) { sh[l][warp] = x; sh[5 + l][warp] = y; }
    }
    __syncthreads();
    if (tid == 0) {
        double S[5], C[5];
        #pragma unroll
        for (int l = 0; l < 5; l++) {
            S[l] = sh[l][0] + sh[l][1];
            C[l] = sh[5 + l][0] + sh[5 + l][1];
        }
        const double w[5] = {(double)0.0448f, (double)0.2856f, (double)0.3001f,
                             (double)0.2363f, (double)0.1333f};
        double cnt4 = (double)NC * 32.0 * 32.0;
        double ss4 = (S[4] / cnt4 + 1.0) * 0.5;
        double p2 = pow(ss4, w[4]);

        double res = 1.0;
        #pragma unroll
        for (int i = 0; i < 4; i++) {
            int dim = 512 >> i;
            double cnt = (double)NC * (double)dim * (double)dim;
            double m = (C[i] / cnt + 1.0) * 0.5;
            res *= pow(m, w[i]) * p2;
        }
        out[0] = (float)res;
    }
}

extern "C" void kernel_launch(void* const* d_in, const int* in_sizes, int n_in,
                              void* d_out, int out_size)
{
    const float* img1 = (const float*)d_in[0];
    const float* img2 = (const float*)d_in[1];
    float* out = (float*)d_out;

    float2* part0; cudaGetSymbolAddress((void**)&part0, g_part0);
    float2* part1; cudaGetSymbolAddress((void**)&part1, g_part1);
    float2* part2; cudaGetSymbolAddress((void**)&part2, g_part2);
    float2* part3; cudaGetSymbolAddress((void**)&part3, g_part3);

    dim3 blk(32, 8);
    ssim_big<true><<<dim3(16, 8, NC), blk>>>(img1, img2, 0, OFF_L1, 512, 512, part0);
    ssim_big<false><<<dim3(8, 4, NC), blk>>>(nullptr, nullptr, OFF_L1, OFF_L2, 256, 256, part1);
    ssim_big<false><<<dim3(4, 2, NC), blk>>>(nullptr, nullptr, OFF_L2, OFF_L3, 128, 128, part2);
    ssim_big<false><<<dim3(2, 1, NC), blk>>>(nullptr, nullptr, OFF_L3, OFF_L4, 64, 64, part3);
    ssim_tail<<<NC, blk>>>();
    mid_reduce<<<48, 256>>>();
    final_combine<<<1, 64>>>(out);
}

// round 13
// speedup vs baseline: 1.3168x; 1.1591x over previous
#include <cuda_runtime.h>
#include <math.h>

// ---------------------------------------------------------------------------
// MS-SSIM on (32,3,512,512) fp32, 5 levels, in (s,d)=(x+y, x-y) basis.
// ssim_big (L0..L3): 32x64 tile, 288 threads (32x9): stage-2 = exactly ONE
//   task per thread per half (no warp imbalance at the barriers); direct
//   global reads (L1-cached), 19KB hAB moment band in smem, permuted STS.
// ssim_tail (L4): one block per plane, 10KB smem.
// Reduction: per-block partial stores -> 48-block mid-reduce -> tiny combine.
// ---------------------------------------------------------------------------

#define NC 96
#define L1_PER 65536            // 256*256
#define L2_PER 16384            // 128*128
#define L3_PER 4096             // 64*64
#define L4_PER 1024             // 32*32
#define OFF_L1 0
#define OFF_L2 (NC * L1_PER)
#define OFF_L3 (OFF_L2 + NC * L2_PER)
#define OFF_L4 (OFF_L3 + NC * L3_PER)
#define SD_TOT (OFF_L4 + NC * L4_PER)

#define NPART0 (16 * 8 * NC)    // 12288
#define NPART1 (8 * 4 * NC)     // 3072
#define NPART2 (4 * 2 * NC)     // 768
#define NPART3 (2 * 1 * NC)     // 192
#define NPART4 NC               // 96

__device__ __align__(16) float2 g_sd[SD_TOT];
__device__ float2 g_part0[NPART0];
__device__ float2 g_part1[NPART1];
__device__ float2 g_part2[NPART2];
__device__ float2 g_part3[NPART3];
__device__ float2 g_part4[NPART4];
__device__ double2 g_mid[48][5];

#define GW0 0.12007838424321349f
#define GW1 0.23388075658535032f
#define GW2 0.29208171834287243f
#define C1V (0.01f * 0.01f)
#define C2V (0.03f * 0.03f)

typedef unsigned long long u64;

__device__ __forceinline__ u64 pk2(float lo, float hi) {
    u64 r; asm("mov.b64 %0, {%1, %2};" : "=l"(r) : "f"(lo), "f"(hi)); return r;
}
__device__ __forceinline__ void upk2(u64 v, float& lo, float& hi) {
    asm("mov.b64 {%0, %1}, %2;" : "=f"(lo), "=f"(hi) : "l"(v));
}
__device__ __forceinline__ u64 fma2_(u64 a, u64 b, u64 c) {
    u64 d; asm("fma.rn.f32x2 %0, %1, %2, %3;" : "=l"(d) : "l"(a), "l"(b), "l"(c)); return d;
}
__device__ __forceinline__ u64 mul2_(u64 a, u64 b) {
    u64 d; asm("mul.rn.f32x2 %0, %1, %2;" : "=l"(d) : "l"(a), "l"(b)); return d;
}
__device__ __forceinline__ u64 add2_(u64 a, u64 b) {
    u64 d; asm("add.rn.f32x2 %0, %1, %2;" : "=l"(d) : "l"(a), "l"(b)); return d;
}
__device__ __forceinline__ float rcpa(float x) {
    float r; asm("rcp.approx.f32 %0, %1;" : "=f"(r) : "f"(x)); return r;
}

__device__ __forceinline__ void ssim_px(u64 mu, u64 sq, float& sa, float& ca)
{
    float ms2, md2; upk2(mul2_(mu, mu), ms2, md2);
    float es, ed;  upk2(sq, es, ed);
    float dm = ms2 - md2;
    float sm = ms2 + md2;
    float lnum = fmaf(0.5f, dm, C1V);
    float lden = fmaf(0.5f, sm, C1V);
    float csn  = fmaf(0.5f, (es - ed) - dm, C2V);
    float csd  = fmaf(0.5f, (es + ed) - sm, C2V);
    float r = rcpa(csd * lden);
    ca = fmaf(csn * lden, r, ca);
    sa = fmaf(csn * lnum, r, sa);
}

// horizontal 5-tap packed moments (tail kernel only)
__device__ __forceinline__ void hmom(const float2* __restrict__ p,
                                     u64 w0p, u64 w1p, u64 w2p,
                                     u64& a_sd, u64& a_sq)
{
    a_sd = 0ull; a_sq = 0ull;
    #pragma unroll
    for (int k = 0; k < 5; k++) {
        u64 v = *reinterpret_cast<const u64*>(p + k);
        u64 wp = (k == 0 || k == 4) ? w0p : ((k == 1 || k == 3) ? w1p : w2p);
        a_sd = fma2_(wp, v, a_sd);
        a_sq = fma2_(wp, mul2_(v, v), a_sq);
    }
}

// ---------------------------------------------------------------------------
// Big-level kernel (levels 0..3): 32-wide x 64-tall tile, 288 threads (32x9).
// smem: hAB[36][33] ulonglong2 = 19008 B only.
// ---------------------------------------------------------------------------
template<bool EXT>
__global__ void __launch_bounds__(288, 5)
ssim_big(const float* __restrict__ ext1, const float* __restrict__ ext2,
         int inOff, int outOff, int W, int H, float2* __restrict__ part)
{
    __shared__ ulonglong2 hAB[36 * 33];
    __shared__ float red[2][9];

    const int tx = threadIdx.x, ty = threadIdx.y;
    const int tid = ty * 32 + tx;           // 0..287
    const int ox = blockIdx.x * 32, oy = blockIdx.y * 64;
    const int plane = blockIdx.z;

    const u64 w0p = pk2(GW0, GW0), w1p = pk2(GW1, GW1), w2p = pk2(GW2, GW2);
    const u64 quarter = pk2(0.25f, 0.25f);

    const size_t planeOff = (size_t)plane * W * H;
    const float2* src = g_sd + inOff + planeOff;   // used when !EXT
    const float* p1 = EXT ? (ext1 + planeOff) : nullptr;
    const float* p2 = EXT ? (ext2 + planeOff) : nullptr;

    // ---- fused 2x2 avg-pool (direct from global; region always in-image) ----
    if (tid < 256) {
        int pr = tid >> 3, pc2 = tid & 7;    // input rows oy+2pr..+1, cols ox+4pc2..+3
        int Wh = W >> 1;
        size_t o = (size_t)outOff + (size_t)plane * (Wh * (H >> 1))
                 + (size_t)(oy / 2 + pr) * Wh + (ox / 2) + 2 * pc2;
        if (EXT) {
            const float* q1 = p1 + (size_t)(oy + 2 * pr) * W + ox + 4 * pc2;
            const float* q2 = p2 + (size_t)(oy + 2 * pr) * W + ox + 4 * pc2;
            float4 a0 = *reinterpret_cast<const float4*>(q1);
            float4 a1 = *reinterpret_cast<const float4*>(q1 + W);
            float4 b0 = *reinterpret_cast<const float4*>(q2);
            float4 b1 = *reinterpret_cast<const float4*>(q2 + W);
            float sA0 = a0.x + a0.y + a1.x + a1.y;
            float sA1 = a0.z + a0.w + a1.z + a1.w;
            float sB0 = b0.x + b0.y + b1.x + b1.y;
            float sB1 = b0.z + b0.w + b1.z + b1.w;
            float4 outv = make_float4(0.25f * (sA0 + sB0), 0.25f * (sA0 - sB0),
                                      0.25f * (sA1 + sB1), 0.25f * (sA1 - sB1));
            *reinterpret_cast<float4*>(&g_sd[o]) = outv;
        } else {
            const float2* q = src + (size_t)(oy + 2 * pr) * W + ox + 4 * pc2;
            ulonglong2 A = *reinterpret_cast<const ulonglong2*>(q);
            ulonglong2 B = *reinterpret_cast<const ulonglong2*>(q + 2);
            ulonglong2 C = *reinterpret_cast<const ulonglong2*>(q + W);
            ulonglong2 D = *reinterpret_cast<const ulonglong2*>(q + W + 2);
            ulonglong2 outv;
            outv.x = mul2_(quarter, add2_(add2_(A.x, A.y), add2_(C.x, C.y)));
            outv.y = mul2_(quarter, add2_(add2_(B.x, B.y), add2_(D.x, D.y)));
            *reinterpret_cast<ulonglong2*>(&g_sd[o]) = outv;
        }
    }

    float sacc = 0.f, cacc = 0.f;

    #pragma unroll
    for (int h = 0; h < 2; h++) {
        // ---- stage 2: horizontal moments, exactly ONE task per thread ----
        // task tid = rl*8 + g ; rl in 0..35 (halo rows), g in 0..7 (col group)
        {
            int rl = tid >> 3, g = tid & 7;
            int gy = oy + h * 32 + rl - 2;
            int c0 = ox + 4 * g - 2;             // first needed input col
            u64 v[8];
            if ((gy >= 0) & (gy < H)) {
                if (EXT) {
                    if (c0 >= 2 && c0 + 9 < W) {
                        const float* q1 = p1 + (size_t)gy * W + (c0 - 2);
                        const float* q2 = p2 + (size_t)gy * W + (c0 - 2);
                        float4 A0 = *reinterpret_cast<const float4*>(q1);
                        float4 B0 = *reinterpret_cast<const float4*>(q2);
                        v[0] = pk2(A0.z + B0.z, A0.z - B0.z);
                        v[1] = pk2(A0.w + B0.w, A0.w - B0.w);
                        float4 A1 = *reinterpret_cast<const float4*>(q1 + 4);
                        float4 B1 = *reinterpret_cast<const float4*>(q2 + 4);
                        v[2] = pk2(A1.x + B1.x, A1.x - B1.x);
                        v[3] = pk2(A1.y + B1.y, A1.y - B1.y);
                        v[4] = pk2(A1.z + B1.z, A1.z - B1.z);
                        v[5] = pk2(A1.w + B1.w, A1.w - B1.w);
                        float4 A2 = *reinterpret_cast<const float4*>(q1 + 8);
                        float4 B2 = *reinterpret_cast<const float4*>(q2 + 8);
                        v[6] = pk2(A2.x + B2.x, A2.x - B2.x);
                        v[7] = pk2(A2.y + B2.y, A2.y - B2.y);
                    } else {
                        #pragma unroll
                        for (int e = 0; e < 8; e++) {
                            int c = c0 + e;
                            float av = 0.f, bv = 0.f;
                            if ((c >= 0) & (c < W)) {
                                size_t ix = (size_t)gy * W + c;
                                av = p1[ix]; bv = p2[ix];
                            }
                            v[e] = pk2(av + bv, av - bv);
                        }
                    }
                } else {
                    if (c0 >= 0 && c0 + 8 <= W) {
                        const ulonglong2* q =
                            reinterpret_cast<const ulonglong2*>(src + (size_t)gy * W + c0);
                        ulonglong2 q0 = q[0], q1v = q[1], q2v = q[2], q3v = q[3];
                        v[0] = q0.x;  v[1] = q0.y;
                        v[2] = q1v.x; v[3] = q1v.y;
                        v[4] = q2v.x; v[5] = q2v.y;
                        v[6] = q3v.x; v[7] = q3v.y;
                    } else {
                        #pragma unroll
                        for (int e = 0; e < 8; e++) {
                            int c = c0 + e;
                            v[e] = ((c >= 0) & (c < W))
                                 ? *reinterpret_cast<const u64*>(src + (size_t)gy * W + c)
                                 : 0ull;
                        }
                    }
                }
            } else {
                #pragma unroll
                for (int e = 0; e < 8; e++) v[e] = 0ull;
            }

            u64 vs[8];
            #pragma unroll
            for (int i = 0; i < 8; i++) vs[i] = mul2_(v[i], v[i]);
            #pragma unroll
            for (int o = 0; o < 4; o++) {
                u64 asd = 0ull, asq = 0ull;
                #pragma unroll
                for (int k = 0; k < 5; k++) {
                    u64 wp = (k == 0 || k == 4) ? w0p : ((k == 1 || k == 3) ? w1p : w2p);
                    asd = fma2_(wp, v[o + k], asd);
                    asq = fma2_(wp, vs[o + k], asq);
                }
                // logical col 4g+o stored at physical col g+8o (conflict-free)
                hAB[rl * 33 + g + 8 * o] = make_ulonglong2(asd, asq);
            }
        }
        __syncthreads();

        // ---- stage 3: vertical ring, warps 0-7, 4 output rows per thread ----
        if (ty < 8) {
            const int b = ty * 4;
            ulonglong2 ring[5];
            #pragma unroll
            for (int j = 0; j < 5; j++)
                ring[j] = hAB[(b + j) * 33 + tx];

            #pragma unroll
            for (int i = 0; i < 4; i++) {
                if (i > 0) {
                    int sl = (i + 4) % 5;
                    ring[sl] = hAB[(b + i + 4) * 33 + tx];
                }
                u64 mu = 0ull, sq = 0ull;
                #pragma unroll
                for (int k = 0; k < 5; k++) {
                    int sl = (i + k) % 5;
                    u64 wp = (k == 0 || k == 4) ? w0p : ((k == 1 || k == 3) ? w1p : w2p);
                    mu = fma2_(wp, ring[sl].x, mu);
                    sq = fma2_(wp, ring[sl].y, sq);
                }
                ssim_px(mu, sq, sacc, cacc);
            }
        }
        __syncthreads();
    }

    // ---- reduction -> per-block partial store ----
    #pragma unroll
    for (int off = 16; off; off >>= 1) {
        sacc += __shfl_down_sync(0xffffffffu, sacc, off);
        cacc += __shfl_down_sync(0xffffffffu, cacc, off);
    }
    if (tx == 0) { red[0][ty] = sacc; red[1][ty] = cacc; }
    __syncthreads();
    if (tid == 0) {
        float ss = 0.f, cc = 0.f;
        #pragma unroll
        for (int i = 0; i < 9; i++) { ss += red[0][i]; cc += red[1][i]; }
        int bid = blockIdx.x + gridDim.x * (blockIdx.y + gridDim.y * blockIdx.z);
        part[bid] = make_float2(ss, cc);
    }
}

// ---------------------------------------------------------------------------
// Plane SSIM helper (tail): per-column hmom + vertical ring.
// ---------------------------------------------------------------------------
template<int S, int NW>
__device__ __forceinline__ void ssim_plane(const float2* __restrict__ P, int stride,
                                           int tx, int ty, float& sa, float& ca)
{
    constexpr int RPT = S / NW;
    const u64 w0p = pk2(GW0, GW0), w1p = pk2(GW1, GW1), w2p = pk2(GW2, GW2);

    #pragma unroll
    for (int ct = 0; ct < S / 32; ct++) {
        int c = tx + 32 * ct;
        int r0 = ty * RPT;
        u64 m_sd[5], m_sq[5];

        #pragma unroll
        for (int j = 0; j < 5; j++)
            hmom(P + (r0 + j) * stride + c, w0p, w1p, w2p, m_sd[j], m_sq[j]);

        #pragma unroll
        for (int i = 0; i < RPT; i++) {
            if (i > 0) {
                int sl = (i + 4) % 5;
                hmom(P + (r0 + i + 4) * stride + c, w0p, w1p, w2p, m_sd[sl], m_sq[sl]);
            }
            u64 mu = 0ull, sq = 0ull;
            #pragma unroll
            for (int k = 0; k < 5; k++) {
                int sl = (i + k) % 5;
                u64 wp = (k == 0 || k == 4) ? w0p : ((k == 1 || k == 3) ? w1p : w2p);
                mu = fma2_(wp, m_sd[sl], mu);
                sq = fma2_(wp, m_sq[sl], sq);
            }
            ssim_px(mu, sq, sa, ca);
        }
    }
}

// ---------------------------------------------------------------------------
// Tail kernel: level 4 only — one block per plane, 256 threads, 10.4KB smem.
// ---------------------------------------------------------------------------
__global__ void __launch_bounds__(256)
ssim_tail()
{
    __shared__ __align__(16) float2 A[36 * 36];
    __shared__ float red[2][8];

    const int tx = threadIdx.x, ty = threadIdx.y;
    const int tid = ty * 32 + tx;
    const int plane = blockIdx.x;

    const float2* src = g_sd + OFF_L4 + (size_t)plane * L4_PER;

    for (int idx = tid; idx < 1296; idx += 256) A[idx] = make_float2(0.f, 0.f);
    __syncthreads();
    for (int idx = tid; idx < 512; idx += 256) {
        int r = idx >> 4, c4 = idx & 15;
        *reinterpret_cast<float4*>(&A[(r + 2) * 36 + 2 + 2 * c4]) =
            *reinterpret_cast<const float4*>(src + r * 32 + 2 * c4);
    }
    __syncthreads();

    float s4 = 0.f, c4v = 0.f;
    ssim_plane<32, 8>(A, 36, tx, ty, s4, c4v);

    #pragma unroll
    for (int off = 16; off; off >>= 1) {
        s4  += __shfl_down_sync(0xffffffffu, s4, off);
        c4v += __shfl_down_sync(0xffffffffu, c4v, off);
    }
    if (tx == 0) { red[0][ty] = s4; red[1][ty] = c4v; }
    __syncthreads();
    if (tid == 0) {
        float ss = 0.f, cc = 0.f;
        #pragma unroll
        for (int i = 0; i < 8; i++) { ss += red[0][i]; cc += red[1][i]; }
        g_part4[plane] = make_float2(ss, cc);
    }
}

// ---------------------------------------------------------------------------
// Mid-reduce: 48 blocks x 256 threads; own slot -> no atomics.
// ---------------------------------------------------------------------------
__global__ void __launch_bounds__(256)
mid_reduce()
{
    const int tid = threadIdx.x, bid = blockIdx.x;
    const int lane = tid & 31, warp = tid >> 5;
    const int g = bid * 256 + tid;       // 0..12287
    __shared__ double sh[10][8];

    double s[5] = {0, 0, 0, 0, 0}, c[5] = {0, 0, 0, 0, 0};
    { float2 v = g_part0[g]; s[0] = v.x; c[0] = v.y; }
    if (g < NPART1) { float2 v = g_part1[g]; s[1] = v.x; c[1] = v.y; }
    if (g < NPART2) { float2 v = g_part2[g]; s[2] = v.x; c[2] = v.y; }
    if (g < NPART3) { float2 v = g_part3[g]; s[3] = v.x; c[3] = v.y; }
    if (g < NPART4) { float2 v = g_part4[g]; s[4] = v.x; c[4] = v.y; }

    #pragma unroll
    for (int l = 0; l < 5; l++) {
        double x = s[l], y = c[l];
        #pragma unroll
        for (int off = 16; off; off >>= 1) {
            x += __shfl_down_sync(0xffffffffu, x, off);
            y += __shfl_down_sync(0xffffffffu, y, off);
        }
        if (lane == 0) { sh[l][warp] = x; sh[5 + l][warp] = y; }
    }
    __syncthreads();
    if (tid < 5) {
        double x = 0, y = 0;
        #pragma unroll
        for (int w = 0; w < 8; w++) { x += sh[tid][w]; y += sh[5 + tid][w]; }
        g_mid[bid][tid] = make_double2(x, y);
    }
}

__global__ void __launch_bounds__(64)
final_combine(float* __restrict__ out)
{
    const int tid = threadIdx.x;
    const int lane = tid & 31, warp = tid >> 5;
    __shared__ double sh[10][2];

    double s[5] = {0, 0, 0, 0, 0}, c[5] = {0, 0, 0, 0, 0};
    if (tid < 48) {
        #pragma unroll
        for (int l = 0; l < 5; l++) {
            double2 v = g_mid[tid][l];
            s[l] = v.x; c[l] = v.y;
        }
    }
    #pragma unroll
    for (int l = 0; l < 5; l++) {
        double x = s[l], y = c[l];
        #pragma unroll
        for (int off = 16; off; off >>= 1) {
            x += __shfl_down_sync(0xffffffffu, x, off);
            y += __shfl_down_sync(0xffffffffu, y, off);
        }
        if (lane == 0) { sh[l][warp] = x; sh[5 + l][warp] = y; }
    }
    __syncthreads();
    if (tid == 0) {
        double S[5], C[5];
        #pragma unroll
        for (int l = 0; l < 5; l++) {
            S[l] = sh[l][0] + sh[l][1];
            C[l] = sh[5 + l][0] + sh[5 + l][1];
        }
        const double w[5] = {(double)0.0448f, (double)0.2856f, (double)0.3001f,
                             (double)0.2363f, (double)0.1333f};
        double cnt4 = (double)NC * 32.0 * 32.0;
        double ss4 = (S[4] / cnt4 + 1.0) * 0.5;
        double p2 = pow(ss4, w[4]);

        double res = 1.0;
        #pragma unroll
        for (int i = 0; i < 4; i++) {
            int dim = 512 >> i;
            double cnt = (double)NC * (double)dim * (double)dim;
            double m = (C[i] / cnt + 1.0) * 0.5;
            res *= pow(m, w[i]) * p2;
        }
        out[0] = (float)res;
    }
}

extern "C" void kernel_launch(void* const* d_in, const int* in_sizes, int n_in,
                              void* d_out, int out_size)
{
    const float* img1 = (const float*)d_in[0];
    const float* img2 = (const float*)d_in[1];
    float* out = (float*)d_out;

    float2* part0; cudaGetSymbolAddress((void**)&part0, g_part0);
    float2* part1; cudaGetSymbolAddress((void**)&part1, g_part1);
    float2* part2; cudaGetSymbolAddress((void**)&part2, g_part2);
    float2* part3; cudaGetSymbolAddress((void**)&part3, g_part3);

    dim3 blk(32, 9);
    ssim_big<true><<<dim3(16, 8, NC), blk>>>(img1, img2, 0, OFF_L1, 512, 512, part0);
    ssim_big<false><<<dim3(8, 4, NC), blk>>>(nullptr, nullptr, OFF_L1, OFF_L2, 256, 256, part1);
    ssim_big<false><<<dim3(4, 2, NC), blk>>>(nullptr, nullptr, OFF_L2, OFF_L3, 128, 128, part2);
    ssim_big<false><<<dim3(2, 1, NC), blk>>>(nullptr, nullptr, OFF_L3, OFF_L4, 64, 64, part3);
    ssim_tail<<<NC, dim3(32, 8)>>>();
    mid_reduce<<<48, 256>>>();
    final_combine<<<1, 64>>>(out);
}